// round 10
// baseline (speedup 1.0000x reference)
#include <cuda_runtime.h>
#include <cuda_bf16.h>
#include <cuda_fp16.h>
#include <cstdint>

// Problem constants (fixed by setup_inputs)
#define BATCH 2048
#define FDIM  2048
#define NKERN 128
#define NDIM  16
#define NCOL  2048

#define LOG2E 1.4426950408889634f

// __device__ scratch (no allocs allowed)
__device__ __half         g_Mh[BATCH * NCOL];    // M * log2e, fp16 (8 MB)
__device__ __nv_bfloat16  g_xb[BATCH * FDIM];    // x in bf16, [M][K] K-major
__device__ __nv_bfloat16  g_wb[NCOL * FDIM];     // W^T in bf16, [N][K] K-major

// ============================================================================
// Conversion kernels
// ============================================================================
__global__ __launch_bounds__(256)
void convert_x_kernel(const float* __restrict__ x) {
    int i = blockIdx.x * blockDim.x + threadIdx.x;   // float4 index
    float4 v = ((const float4*)x)[i];
    __nv_bfloat162 lo = __floats2bfloat162_rn(v.x, v.y);
    __nv_bfloat162 hi = __floats2bfloat162_rn(v.z, v.w);
    uint2 pk;
    pk.x = *(uint32_t*)&lo;
    pk.y = *(uint32_t*)&hi;
    ((uint2*)g_xb)[i] = pk;
}

// W [K][N] fp32  ->  g_wb [N][K] bf16 (tiled transpose)
__global__ __launch_bounds__(256)
void convert_wt_kernel(const float* __restrict__ W) {
    __shared__ float tile[32][33];
    const int n0 = blockIdx.x * 32, k0 = blockIdx.y * 32;
    const int tx = threadIdx.x, ty = threadIdx.y;   // 32 x 8
#pragma unroll
    for (int j = ty; j < 32; j += 8)
        tile[j][tx] = W[(size_t)(k0 + j) * NCOL + n0 + tx];
    __syncthreads();
#pragma unroll
    for (int j = ty; j < 32; j += 8)
        g_wb[(size_t)(n0 + j) * FDIM + k0 + tx] = __float2bfloat16_rn(tile[tx][j]);
}

// ============================================================================
// bf16 mma.sync GEMM: M = g_xb @ g_wb^T, epilogue stores M*log2e as fp16.
// 128x128 CTA tile, BK=32, 256 threads (8 warps, 2M x 4N), 3-stage cp.async.
// ============================================================================
#define BK      32
#define STRIDE  40                       // halves per smem row (80 B, conflict-free)
#define STAGE_HALVES (128 * STRIDE)      // per matrix per stage
#define STAGE_BYTES  (2 * STAGE_HALVES * 2)   // A + B
#define NSTAGE  3
#define GEMM_SMEM (NSTAGE * STAGE_BYTES)      // 61440 B

__device__ __forceinline__ void cp_async16(uint32_t dst, const void* src) {
    asm volatile("cp.async.cg.shared.global [%0], [%1], 16;"
                 :: "r"(dst), "l"(src) : "memory");
}
__device__ __forceinline__ void cp_commit() {
    asm volatile("cp.async.commit_group;" ::: "memory");
}
template <int N>
__device__ __forceinline__ void cp_wait() {
    asm volatile("cp.async.wait_group %0;" :: "n"(N) : "memory");
}

__device__ __forceinline__ void ldm_x4(uint32_t addr, uint32_t& r0, uint32_t& r1,
                                       uint32_t& r2, uint32_t& r3) {
    asm volatile("ldmatrix.sync.aligned.m8n8.x4.shared.b16 {%0,%1,%2,%3}, [%4];"
                 : "=r"(r0), "=r"(r1), "=r"(r2), "=r"(r3) : "r"(addr));
}

__device__ __forceinline__ void mma_16816(float* d, const uint32_t* a,
                                          const uint32_t* b) {
    asm volatile(
        "mma.sync.aligned.m16n8k16.row.col.f32.bf16.bf16.f32 "
        "{%0,%1,%2,%3}, {%4,%5,%6,%7}, {%8,%9}, {%0,%1,%2,%3};"
        : "+f"(d[0]), "+f"(d[1]), "+f"(d[2]), "+f"(d[3])
        : "r"(a[0]), "r"(a[1]), "r"(a[2]), "r"(a[3]), "r"(b[0]), "r"(b[1]));
}

// Issue the cp.async loads for one k-chunk into stage buffer `sbase`.
__device__ __forceinline__ void issue_loads(uint32_t sA, uint32_t sB,
                                            int bRow, int bCol, int k0, int tid) {
#pragma unroll
    for (int i = 0; i < 2; i++) {
        int id  = tid * 2 + i;           // 0..511
        int row = id >> 2;               // 0..127
        int c   = id & 3;                // 16B chunk within 64B row
        uint32_t off = row * (STRIDE * 2) + c * 16;
        cp_async16(sA + off, g_xb + (size_t)(bRow + row) * FDIM + k0 + c * 8);
        cp_async16(sB + off, g_wb + (size_t)(bCol + row) * FDIM + k0 + c * 8);
    }
}

__global__ __launch_bounds__(256, 2)
void mbd_mma_gemm() {
    extern __shared__ __align__(128) char smem[];
    const uint32_t sbase = (uint32_t)__cvta_generic_to_shared(smem);

    const int tid  = threadIdx.x;
    const int wid  = tid >> 5;
    const int lane = tid & 31;
    const int bRow = blockIdx.y * 128;
    const int bCol = blockIdx.x * 128;
    const int wm   = (wid & 1) * 64;     // warp M offset in tile
    const int wn   = (wid >> 1) * 32;    // warp N offset in tile

    uint32_t stA[NSTAGE], stB[NSTAGE];
#pragma unroll
    for (int s = 0; s < NSTAGE; s++) {
        stA[s] = sbase + s * STAGE_BYTES;
        stB[s] = stA[s] + STAGE_HALVES * 2;
    }

    float acc[4][4][4];
#pragma unroll
    for (int i = 0; i < 4; i++)
#pragma unroll
        for (int j = 0; j < 4; j++)
#pragma unroll
            for (int q = 0; q < 4; q++) acc[i][j][q] = 0.0f;

    // Prologue: stages 0..NSTAGE-2 in flight
#pragma unroll
    for (int s = 0; s < NSTAGE - 1; s++) {
        issue_loads(stA[s], stB[s], bRow, bCol, s * BK, tid);
        cp_commit();
    }

    // Per-thread ldmatrix source offsets (within a stage buffer, in bytes):
    const uint32_t aoff = (uint32_t)((lane & 15) * STRIDE + (lane >> 4) * 8) * 2;
    const uint32_t boff = (uint32_t)(((lane >> 4) * 8 + (lane & 7)) * STRIDE
                                     + ((lane >> 3) & 1) * 8) * 2;

    const int T = FDIM / BK;             // 64
#pragma unroll 1
    for (int t = 0; t < T; t++) {
        cp_wait<NSTAGE - 2>();           // stage t resident
        __syncthreads();                 // also fences slot reuse

        if (t + NSTAGE - 1 < T) {
            int s = (t + NSTAGE - 1) % NSTAGE;
            issue_loads(stA[s], stB[s], bRow, bCol, (t + NSTAGE - 1) * BK, tid);
        }
        cp_commit();                     // keep group count in lockstep

        const int cs = t % NSTAGE;
        const uint32_t cA = stA[cs] + aoff;
        const uint32_t cB = stB[cs] + boff;

#pragma unroll
        for (int ks = 0; ks < 2; ks++) {
            uint32_t a[4][4], b[2][4];
#pragma unroll
            for (int mf = 0; mf < 4; mf++)
                ldm_x4(cA + ((mf + (wm >> 4)) * 16 * STRIDE + ks * 16) * 2,
                       a[mf][0], a[mf][1], a[mf][2], a[mf][3]);
#pragma unroll
            for (int p = 0; p < 2; p++)
                ldm_x4(cB + ((wn + p * 16) * STRIDE + ks * 16) * 2,
                       b[p][0], b[p][1], b[p][2], b[p][3]);
#pragma unroll
            for (int mf = 0; mf < 4; mf++) {
#pragma unroll
                for (int nf = 0; nf < 4; nf++) {
                    const uint32_t* bf = &b[nf >> 1][(nf & 1) * 2];
                    mma_16816(acc[mf][nf], a[mf], bf);
                }
            }
        }
    }

    // Epilogue: scale by log2e, pack to fp16, store 32-bit pairs to g_Mh.
    const int r0 = bRow + wm + (lane >> 2);
    const int c0 = bCol + wn + (lane & 3) * 2;
#pragma unroll
    for (int mf = 0; mf < 4; mf++) {
#pragma unroll
        for (int nf = 0; nf < 4; nf++) {
            __half2 p01 = __floats2half2_rn(acc[mf][nf][0] * LOG2E,
                                            acc[mf][nf][1] * LOG2E);
            __half2 p23 = __floats2half2_rn(acc[mf][nf][2] * LOG2E,
                                            acc[mf][nf][3] * LOG2E);
            *(uint32_t*)&g_Mh[(size_t)(r0 + mf * 16)     * NCOL + c0 + nf * 8] =
                *(uint32_t*)&p01;
            *(uint32_t*)&g_Mh[(size_t)(r0 + mf * 16 + 8) * NCOL + c0 + nf * 8] =
                *(uint32_t*)&p23;
        }
    }
}

// ============================================================================
// Kernel 2: pairwise L1 + exp2, packed half2. 256 threads = 2 batch rows/CTA
// (better issue utilization), 4 independent accumulators.
// ============================================================================
__global__ __launch_bounds__(256)
void mbd_pairwise_kernel(float* __restrict__ out)
{
    __shared__ __align__(16) __half2 sMh[2][NKERN * 8];   // 2 x 4 KB

    const int half_id = threadIdx.x >> 7;        // 0 or 1 (warps 0-3 / 4-7)
    const int i       = threadIdx.x & 127;       // kernel index within row
    const int b       = blockIdx.x * 2 + half_id;

    const uint4* Mb = (const uint4*)&g_Mh[(size_t)b * NCOL];
    ((uint4*)sMh[half_id])[i]       = Mb[i];
    ((uint4*)sMh[half_id])[i + 128] = Mb[i + 128];
    __syncthreads();

    const __half2* sRow = sMh[half_id];
    __half2 mi[8];
#pragma unroll
    for (int q = 0; q < 8; q++) mi[q] = sRow[i * 8 + q];

    float a0 = 0.f, a1 = 0.f, a2 = 0.f, a3 = 0.f;
#pragma unroll 1
    for (int j = 0; j < NKERN; j += 4) {
#pragma unroll
        for (int u = 0; u < 4; u++) {
            uint4 u0 = *(const uint4*)&sRow[(j + u) * 8];
            uint4 u1 = *(const uint4*)&sRow[(j + u) * 8 + 4];
            __half2 m0 = *(__half2*)&u0.x, m1 = *(__half2*)&u0.y;
            __half2 m2 = *(__half2*)&u0.z, m3 = *(__half2*)&u0.w;
            __half2 m4 = *(__half2*)&u1.x, m5 = *(__half2*)&u1.y;
            __half2 m6 = *(__half2*)&u1.z, m7 = *(__half2*)&u1.w;

            __half2 d0 = __habs2(__hsub2(mi[0], m0));
            __half2 d1 = __habs2(__hsub2(mi[1], m1));
            __half2 d2 = __habs2(__hsub2(mi[2], m2));
            __half2 d3 = __habs2(__hsub2(mi[3], m3));
            __half2 d4 = __habs2(__hsub2(mi[4], m4));
            __half2 d5 = __habs2(__hsub2(mi[5], m5));
            __half2 d6 = __habs2(__hsub2(mi[6], m6));
            __half2 d7 = __habs2(__hsub2(mi[7], m7));

            __half2 e0 = __hadd2(d0, d1);
            __half2 e1 = __hadd2(d2, d3);
            __half2 e2 = __hadd2(d4, d5);
            __half2 e3 = __hadd2(d6, d7);
            __half2 f0 = __hadd2(e0, e1);
            __half2 f1 = __hadd2(e2, e3);
            __half2 s  = __hadd2(f0, f1);

            __half  hs = __hadd(__low2half(s), __high2half(s));
            float   nf = -__half2float(hs);
            float   e;
            asm("ex2.approx.ftz.f32 %0, %1;" : "=f"(e) : "f"(nf));
            if (u == 0) a0 += e;
            else if (u == 1) a1 += e;
            else if (u == 2) a2 += e;
            else a3 += e;
        }
    }
    out[(size_t)b * NKERN + i] = (a0 + a1) + (a2 + a3);
}

// ============================================================================
extern "C" void kernel_launch(void* const* d_in, const int* in_sizes, int n_in,
                              void* d_out, int out_size)
{
    const float* x = (const float*)d_in[0];   // [2048, 2048]
    const float* W = (const float*)d_in[1];   // [2048, 2048]
    float* out = (float*)d_out;               // [2048, 128]

    convert_x_kernel<<<(BATCH * FDIM / 4) / 256, 256>>>(x);
    convert_wt_kernel<<<dim3(NCOL / 32, FDIM / 32), dim3(32, 8)>>>(W);

    cudaFuncSetAttribute(mbd_mma_gemm,
                         cudaFuncAttributeMaxDynamicSharedMemorySize, GEMM_SMEM);
    mbd_mma_gemm<<<dim3(NCOL / 128, BATCH / 128), 256, GEMM_SMEM>>>();

    mbd_pairwise_kernel<<<BATCH / 2, 256>>>(out);
}